// round 2
// baseline (speedup 1.0000x reference)
#include <cuda_runtime.h>
#include <cuda_bf16.h>
#include <cstdint>

#define BB 2
#define CC 256
#define NN 4096
#define NEGBIG (-3.4028234e38f)

// ---------------- scratch (device globals; no runtime allocation) -------------
__device__ float g_F[(size_t)BB * NN * CC];   // [b, n, c]
__device__ float g_G[(size_t)BB * NN * CC];   // [b, n, c]
__device__ float g_H[(size_t)BB * NN * CC];   // [b, m, c]
__device__ float g_O[(size_t)BB * NN * CC];   // [b, n, c]
__device__ float g_S[(size_t)BB * NN * NN];   // [b, n, m]  (134 MB)
__device__ int   g_idx[BB * NN];
__device__ float g_mean[2 * BB * CC];
__device__ float g_istd[2 * BB * CC];

// ---------------- helpers -----------------------------------------------------
__device__ __forceinline__ float int_or_float(int v) {
    // t1/t2 may arrive as int32 or as float bits; small ints are ints.
    return (v >= -100000 && v <= 100000) ? (float)v : __int_as_float(v);
}

__device__ __forceinline__ int idx8(int base4, int k) {
    return (k < 4) ? (base4 + k) : (64 + base4 + (k - 4));
}

__device__ __forceinline__ void mm_tile(const float (&As)[8][128],
                                        const float (&Bs)[8][128],
                                        int row4, int col4, float (&acc)[8][8]) {
#pragma unroll
    for (int kk = 0; kk < 8; ++kk) {
        float a[8], b[8];
#pragma unroll
        for (int i = 0; i < 4; ++i) { a[i] = As[kk][row4 + i]; a[4 + i] = As[kk][64 + row4 + i]; }
#pragma unroll
        for (int j = 0; j < 4; ++j) { b[j] = Bs[kk][col4 + j]; b[4 + j] = Bs[kk][64 + col4 + j]; }
#pragma unroll
        for (int i = 0; i < 8; ++i)
#pragma unroll
            for (int j = 0; j < 8; ++j) acc[i][j] += a[i] * b[j];
    }
}

// ---------------- stats: per (b,c) mean / inv-std (ddof=1) --------------------
__global__ void __launch_bounds__(256) stats_kernel(const float* __restrict__ x,
                                                    float* __restrict__ meanv,
                                                    float* __restrict__ istdv) {
    int row = blockIdx.x;                 // b*CC + c
    const float* p = x + (size_t)row * NN;
    int t = threadIdx.x;
    float s = 0.f, s2 = 0.f;
    for (int i = t; i < NN; i += 256) { float v = p[i]; s += v; s2 += v * v; }
    __shared__ float sh1[256], sh2[256];
    sh1[t] = s; sh2[t] = s2; __syncthreads();
    for (int o = 128; o > 0; o >>= 1) {
        if (t < o) { sh1[t] += sh1[t + o]; sh2[t] += sh2[t + o]; }
        __syncthreads();
    }
    if (t == 0) {
        float m = sh1[0] / NN;
        float var = (sh2[0] - (float)NN * m * m) / (float)(NN - 1);
        meanv[row] = m;
        istdv[row] = rsqrtf(var + 1e-5f);
    }
}

// ---------------- F/G/H GEMM: out[b,n,c] = sum_k W[c,k]*norm(x[b,k,n]) + bias[c]
__global__ void __launch_bounds__(256) gemm_fgh(const float* __restrict__ x,
                                                const float* __restrict__ W,
                                                const float* __restrict__ bias,
                                                const float* __restrict__ meanv,
                                                const float* __restrict__ istdv,
                                                float* __restrict__ out,
                                                int use_norm) {
    const int b  = blockIdx.z;
    const int n0 = blockIdx.x * 128;
    const int c0 = blockIdx.y * 128;
    __shared__ float As[8][128];   // As[k][n]
    __shared__ float Bs[8][128];   // Bs[k][c]
    const int t = threadIdx.x, tx = t & 15, ty = t >> 4;
    const int row4 = ty * 4, col4 = tx * 4;     // rows=n, cols=c
    const int ai = t & 127, ak0 = t >> 7;       // A loader
    const int lr = t >> 1, lq = (t & 1) * 4;    // B loader (float4)
    const float* xb = x + (size_t)b * CC * NN;
    const float* mb = meanv + b * CC;
    const float* ib = istdv + b * CC;

    float acc[8][8];
#pragma unroll
    for (int i = 0; i < 8; ++i)
#pragma unroll
        for (int j = 0; j < 8; ++j) acc[i][j] = 0.f;

    for (int k0 = 0; k0 < CC; k0 += 8) {
#pragma unroll
        for (int u = 0; u < 4; ++u) {
            int kk = ak0 + 2 * u;
            float v = xb[(size_t)(k0 + kk) * NN + n0 + ai];
            if (use_norm) v = (v - mb[k0 + kk]) * ib[k0 + kk];
            As[kk][ai] = v;
        }
        float4 wv = *(const float4*)(W + (size_t)(c0 + lr) * CC + k0 + lq);
        Bs[lq + 0][lr] = wv.x; Bs[lq + 1][lr] = wv.y;
        Bs[lq + 2][lr] = wv.z; Bs[lq + 3][lr] = wv.w;
        __syncthreads();
        mm_tile(As, Bs, row4, col4, acc);
        __syncthreads();
    }
#pragma unroll
    for (int i = 0; i < 8; ++i) {
        int n = n0 + idx8(row4, i);
        float* op = out + ((size_t)b * NN + n) * CC + c0;
#pragma unroll
        for (int j = 0; j < 8; ++j) {
            int cj = idx8(col4, j);
            op[cj] = acc[i][j] + bias[c0 + cj];
        }
    }
}

// ---------------- score GEMM: S[b,n,m] = sum_c F[b,n,c]*G[b,m,c] --------------
__global__ void __launch_bounds__(256) gemm_score(const float* __restrict__ Fm,
                                                  const float* __restrict__ Gm,
                                                  float* __restrict__ S) {
    const int b  = blockIdx.z;
    const int n0 = blockIdx.y * 128;
    const int m0 = blockIdx.x * 128;
    const float* A = Fm + (size_t)b * NN * CC;
    const float* B = Gm + (size_t)b * NN * CC;
    __shared__ float As[8][128];   // As[k][n]
    __shared__ float Bs[8][128];   // Bs[k][m]
    const int t = threadIdx.x, tx = t & 15, ty = t >> 4;
    const int row4 = ty * 4, col4 = tx * 4;
    const int lr = t >> 1, lq = (t & 1) * 4;

    float acc[8][8];
#pragma unroll
    for (int i = 0; i < 8; ++i)
#pragma unroll
        for (int j = 0; j < 8; ++j) acc[i][j] = 0.f;

    for (int k0 = 0; k0 < CC; k0 += 8) {
        float4 av = *(const float4*)(A + (size_t)(n0 + lr) * CC + k0 + lq);
        float4 bv = *(const float4*)(B + (size_t)(m0 + lr) * CC + k0 + lq);
        As[lq + 0][lr] = av.x; As[lq + 1][lr] = av.y; As[lq + 2][lr] = av.z; As[lq + 3][lr] = av.w;
        Bs[lq + 0][lr] = bv.x; Bs[lq + 1][lr] = bv.y; Bs[lq + 2][lr] = bv.z; Bs[lq + 3][lr] = bv.w;
        __syncthreads();
        mm_tile(As, Bs, row4, col4, acc);
        __syncthreads();
    }
    float* Sp = S + (size_t)b * NN * NN;
#pragma unroll
    for (int i = 0; i < 8; ++i) {
        int n = n0 + idx8(row4, i);
        float* rp = Sp + (size_t)n * NN + m0;
        float4 v0 = make_float4(acc[i][0], acc[i][1], acc[i][2], acc[i][3]);
        float4 v1 = make_float4(acc[i][4], acc[i][5], acc[i][6], acc[i][7]);
        *(float4*)(rp + col4)      = v0;
        *(float4*)(rp + 64 + col4) = v1;
    }
}

// ---------------- masked row softmax (in place) -------------------------------
__global__ void __launch_bounds__(256) softmax_kernel(float* __restrict__ S,
                                                      const float* __restrict__ mask) {
    const int bn = blockIdx.x;
    const int n  = bn & (NN - 1);
    float* row = S + (size_t)bn * NN;
    const float* mrow = mask + (size_t)n * NN;
    const int t = threadIdx.x;
    float v[16];
    float mx = NEGBIG;
#pragma unroll
    for (int r = 0; r < 16; ++r) {
        int i = t + r * 256;
        float sv = row[i];
        v[r] = (mrow[i] < 0.5f) ? NEGBIG : sv;
        mx = fmaxf(mx, v[r]);
    }
    __shared__ float red[256];
    red[t] = mx; __syncthreads();
    for (int o = 128; o > 0; o >>= 1) {
        if (t < o) red[t] = fmaxf(red[t], red[t + o]);
        __syncthreads();
    }
    mx = red[0]; __syncthreads();
    float sum = 0.f;
#pragma unroll
    for (int r = 0; r < 16; ++r) {
        float e = (v[r] > -1e37f) ? expf(v[r] - mx) : 0.f;
        v[r] = e; sum += e;
    }
    red[t] = sum; __syncthreads();
    for (int o = 128; o > 0; o >>= 1) {
        if (t < o) red[t] += red[t + o];
        __syncthreads();
    }
    float inv = 1.f / red[0];
#pragma unroll
    for (int r = 0; r < 16; ++r) row[t + r * 256] = v[r] * inv;
}

// ---------------- masked row argmax -------------------------------------------
__global__ void __launch_bounds__(256) argmax_kernel(const float* __restrict__ S,
                                                     const float* __restrict__ mask,
                                                     int* __restrict__ idxv) {
    const int bn = blockIdx.x;
    const int n  = bn & (NN - 1);
    const float* row = S + (size_t)bn * NN;
    const float* mrow = mask + (size_t)n * NN;
    const int t = threadIdx.x;
    float best = -INFINITY; int bi = 0;
#pragma unroll
    for (int r = 0; r < 16; ++r) {
        int i = t + r * 256;
        float sv = (mrow[i] < 0.5f) ? NEGBIG : row[i];
        if (sv > best || (sv == best && i < bi)) { best = sv; bi = i; }
    }
    __shared__ float rv[256];
    __shared__ int   ri[256];
    rv[t] = best; ri[t] = bi; __syncthreads();
    for (int o = 128; o > 0; o >>= 1) {
        if (t < o) {
            if (rv[t + o] > rv[t] || (rv[t + o] == rv[t] && ri[t + o] < ri[t])) {
                rv[t] = rv[t + o]; ri[t] = ri[t + o];
            }
        }
        __syncthreads();
    }
    if (t == 0) idxv[bn] = ri[0];
}

// ---------------- A·V GEMM: O[b,n,c] = sum_m A[b,n,m]*H[b,m,c] ----------------
__global__ void __launch_bounds__(256) gemm_av(const float* __restrict__ S,
                                               const float* __restrict__ Hm,
                                               float* __restrict__ O) {
    const int b  = blockIdx.z;
    const int n0 = blockIdx.y * 128;
    const int c0 = blockIdx.x * 128;
    const float* A = S + (size_t)b * NN * NN;
    const float* B = Hm + (size_t)b * NN * CC;
    __shared__ float As[8][128];   // As[k][n]
    __shared__ float Bs[8][128];   // Bs[k][c]
    const int t = threadIdx.x, tx = t & 15, ty = t >> 4;
    const int row4 = ty * 4, col4 = tx * 4;
    const int lr = t >> 1, lq = (t & 1) * 4;
    const int ai = t & 127, ak0 = t >> 7;

    float acc[8][8];
#pragma unroll
    for (int i = 0; i < 8; ++i)
#pragma unroll
        for (int j = 0; j < 8; ++j) acc[i][j] = 0.f;

    for (int k0 = 0; k0 < NN; k0 += 8) {
        float4 av = *(const float4*)(A + (size_t)(n0 + lr) * NN + k0 + lq);
        As[lq + 0][lr] = av.x; As[lq + 1][lr] = av.y; As[lq + 2][lr] = av.z; As[lq + 3][lr] = av.w;
#pragma unroll
        for (int u = 0; u < 4; ++u) {
            int kk = ak0 + 2 * u;
            Bs[kk][ai] = B[(size_t)(k0 + kk) * CC + c0 + ai];
        }
        __syncthreads();
        mm_tile(As, Bs, row4, col4, acc);
        __syncthreads();
    }
#pragma unroll
    for (int i = 0; i < 8; ++i) {
        int n = n0 + idx8(row4, i);
        float* op = O + ((size_t)b * NN + n) * CC + c0;
        float4 v0 = make_float4(acc[i][0], acc[i][1], acc[i][2], acc[i][3]);
        float4 v1 = make_float4(acc[i][4], acc[i][5], acc[i][6], acc[i][7]);
        *(float4*)(op + col4)      = v0;
        *(float4*)(op + 64 + col4) = v1;
    }
}

// ---------------- combine: V[b,n,c] = t1*O[b,n,c] + t2*H[b,idx[b,n],c] --------
__global__ void __launch_bounds__(256) combine_kernel(const float* __restrict__ O,
                                                      const float* __restrict__ Hm,
                                                      const int* __restrict__ idxv,
                                                      const int* __restrict__ t1p,
                                                      const int* __restrict__ t2p,
                                                      float* __restrict__ V) {
    const int bn = blockIdx.x;
    const int b  = bn >> 12;
    const float t1f = int_or_float(t1p[0]);
    const float t2f = int_or_float(t2p[0]);
    const int id = idxv[bn];
    const float* op = O + (size_t)bn * CC;
    const float* hp = Hm + ((size_t)b * NN + id) * CC;
    float* vp = V + (size_t)bn * CC;
    for (int c = threadIdx.x; c < CC; c += 256)
        vp[c] = t1f * op[c] + t2f * hp[c];
}

// ---------------- final: out[b,c,n] = sum_k Wo[c,k]*V[b,n,k] + t12*bo[c] + content
__global__ void __launch_bounds__(256) gemm_final(const float* __restrict__ Wo,
                                                  const float* __restrict__ V,
                                                  const float* __restrict__ bo,
                                                  const float* __restrict__ content,
                                                  const int* __restrict__ t1p,
                                                  const int* __restrict__ t2p,
                                                  float* __restrict__ out) {
    const int b  = blockIdx.z;
    const int n0 = blockIdx.x * 128;
    const int c0 = blockIdx.y * 128;
    __shared__ float As[8][128];   // As[k][c]
    __shared__ float Bs[8][128];   // Bs[k][n]
    const int t = threadIdx.x, tx = t & 15, ty = t >> 4;
    const int row4 = ty * 4, col4 = tx * 4;   // rows=c, cols=n
    const int lr = t >> 1, lq = (t & 1) * 4;
    const float* Vb = V + (size_t)b * NN * CC;

    float acc[8][8];
#pragma unroll
    for (int i = 0; i < 8; ++i)
#pragma unroll
        for (int j = 0; j < 8; ++j) acc[i][j] = 0.f;

    for (int k0 = 0; k0 < CC; k0 += 8) {
        float4 av = *(const float4*)(Wo + (size_t)(c0 + lr) * CC + k0 + lq);
        float4 bv = *(const float4*)(Vb + (size_t)(n0 + lr) * CC + k0 + lq);
        As[lq + 0][lr] = av.x; As[lq + 1][lr] = av.y; As[lq + 2][lr] = av.z; As[lq + 3][lr] = av.w;
        Bs[lq + 0][lr] = bv.x; Bs[lq + 1][lr] = bv.y; Bs[lq + 2][lr] = bv.z; Bs[lq + 3][lr] = bv.w;
        __syncthreads();
        mm_tile(As, Bs, row4, col4, acc);
        __syncthreads();
    }
    const float t12 = int_or_float(t1p[0]) + int_or_float(t2p[0]);
#pragma unroll
    for (int i = 0; i < 8; ++i) {
        int c = c0 + idx8(row4, i);
        float bb = t12 * bo[c];
        float* op = out + ((size_t)b * CC + c) * NN + n0;
        const float* cp = content + ((size_t)b * CC + c) * NN + n0;
        float4 c0v = *(const float4*)(cp + col4);
        float4 c1v = *(const float4*)(cp + 64 + col4);
        float4 v0 = make_float4(acc[i][0] + bb + c0v.x, acc[i][1] + bb + c0v.y,
                                acc[i][2] + bb + c0v.z, acc[i][3] + bb + c0v.w);
        float4 v1 = make_float4(acc[i][4] + bb + c1v.x, acc[i][5] + bb + c1v.y,
                                acc[i][6] + bb + c1v.z, acc[i][7] + bb + c1v.w);
        *(float4*)(op + col4)      = v0;
        *(float4*)(op + 64 + col4) = v1;
    }
}

// ---------------- launch -------------------------------------------------------
extern "C" void kernel_launch(void* const* d_in, const int* in_sizes, int n_in,
                              void* d_out, int out_size) {
    (void)in_sizes; (void)n_in; (void)out_size;
    const float* content     = (const float*)d_in[0];
    const float* style       = (const float*)d_in[1];
    const float* content_sem = (const float*)d_in[2];
    const float* style_sem   = (const float*)d_in[3];
    /* d_in[4] = map_32 (unused: h*w == 4096 -> map_64 branch) */
    const float* map64       = (const float*)d_in[5];
    const int*   t1p         = (const int*)d_in[6];
    const int*   t2p         = (const int*)d_in[7];
    const float* Wf = (const float*)d_in[8];   const float* bf = (const float*)d_in[9];
    const float* Wg = (const float*)d_in[10];  const float* bg = (const float*)d_in[11];
    const float* Wh = (const float*)d_in[12];  const float* bh = (const float*)d_in[13];
    const float* Wo = (const float*)d_in[14];  const float* bo = (const float*)d_in[15];
    float* out = (float*)d_out;

    float *pF, *pG, *pH, *pO, *pS, *pMean, *pIstd; int* pIdx;
    cudaGetSymbolAddress((void**)&pF, g_F);
    cudaGetSymbolAddress((void**)&pG, g_G);
    cudaGetSymbolAddress((void**)&pH, g_H);
    cudaGetSymbolAddress((void**)&pO, g_O);
    cudaGetSymbolAddress((void**)&pS, g_S);
    cudaGetSymbolAddress((void**)&pMean, g_mean);
    cudaGetSymbolAddress((void**)&pIstd, g_istd);
    cudaGetSymbolAddress((void**)&pIdx, g_idx);

    const dim3 gFGH(NN / 128, CC / 128, BB);
    const dim3 gSCORE(NN / 128, NN / 128, BB);
    const dim3 gAV(CC / 128, NN / 128, BB);

    // ---- SCA branch (semantic features, soft attention) ----
    stats_kernel<<<BB * CC, 256>>>(content_sem, pMean, pIstd);
    stats_kernel<<<BB * CC, 256>>>(style_sem, pMean + BB * CC, pIstd + BB * CC);
    gemm_fgh<<<gFGH, 256>>>(content_sem, Wf, bf, pMean, pIstd, pF, 1);
    gemm_fgh<<<gFGH, 256>>>(style_sem,  Wg, bg, pMean + BB * CC, pIstd + BB * CC, pG, 1);
    gemm_fgh<<<gFGH, 256>>>(style,      Wh, bh, pMean, pIstd, pH, 0);
    gemm_score<<<gSCORE, 256>>>(pF, pG, pS);
    softmax_kernel<<<BB * NN, 256>>>(pS, map64);
    gemm_av<<<gAV, 256>>>(pS, pH, pO);

    // ---- SSA branch (content/style features, hard argmax == gather) ----
    stats_kernel<<<BB * CC, 256>>>(content, pMean, pIstd);
    stats_kernel<<<BB * CC, 256>>>(style, pMean + BB * CC, pIstd + BB * CC);
    gemm_fgh<<<gFGH, 256>>>(content, Wf, bf, pMean, pIstd, pF, 1);
    gemm_fgh<<<gFGH, 256>>>(style,   Wg, bg, pMean + BB * CC, pIstd + BB * CC, pG, 1);
    gemm_score<<<gSCORE, 256>>>(pF, pG, pS);
    argmax_kernel<<<BB * NN, 256>>>(pS, map64, pIdx);

    // ---- combine + output conv + residual ----
    combine_kernel<<<BB * NN, 256>>>(pO, pH, pIdx, t1p, t2p, pF);   // V -> g_F (reuse)
    gemm_final<<<gFGH, 256>>>(Wo, pF, bo, content, t1p, t2p, out);
}

// round 4
// speedup vs baseline: 1.5323x; 1.5323x over previous
#include <cuda_runtime.h>
#include <cuda_bf16.h>
#include <cstdint>

#define BB 2
#define CC 256
#define NN 4096
#define NEGBIG (-3.4028234e38f)

// ======================= PTX helpers (portable, compute_103-legal) ============
__device__ __forceinline__ uint32_t smem_u32(const void* p) {
    uint32_t a;
    asm("{ .reg .u64 t; cvta.to.shared.u64 t, %1; cvt.u32.u64 %0, t; }" : "=r"(a) : "l"(p));
    return a;
}
__device__ __forceinline__ void cp_async16(uint32_t s, const void* g) {
    asm volatile("cp.async.ca.shared.global [%0], [%1], 16;" :: "r"(s), "l"(g));
}
#define CP_COMMIT() asm volatile("cp.async.commit_group;" ::: "memory")
#define CP_WAIT(n)  asm volatile("cp.async.wait_group %0;" :: "n"(n) : "memory")
__device__ __forceinline__ void ldmx4(uint32_t& r0, uint32_t& r1, uint32_t& r2,
                                      uint32_t& r3, uint32_t a) {
    asm volatile("ldmatrix.sync.aligned.m8n8.x4.shared.b16 {%0,%1,%2,%3}, [%4];"
                 : "=r"(r0), "=r"(r1), "=r"(r2), "=r"(r3) : "r"(a));
}
__device__ __forceinline__ void mma_bf16(float* c, const uint32_t* a, uint32_t b0,
                                         uint32_t b1) {
    asm volatile("mma.sync.aligned.m16n8k16.row.col.f32.bf16.bf16.f32 "
                 "{%0,%1,%2,%3}, {%4,%5,%6,%7}, {%8,%9}, {%0,%1,%2,%3};"
                 : "+f"(c[0]), "+f"(c[1]), "+f"(c[2]), "+f"(c[3])
                 : "r"(a[0]), "r"(a[1]), "r"(a[2]), "r"(a[3]), "r"(b0), "r"(b1));
}

// ======================= scratch ==============================================
__device__ __align__(256) float g_S[(size_t)BB * NN * NN];
__device__ __align__(256) float g_H[(size_t)BB * NN * CC];
__device__ __align__(256) float g_O[(size_t)BB * NN * CC];
__device__ __align__(256) __nv_bfloat16 gF0[(size_t)BB*NN*CC], gF1[(size_t)BB*NN*CC], gF2[(size_t)BB*NN*CC];
__device__ __align__(256) __nv_bfloat16 gG0[(size_t)BB*NN*CC], gG1[(size_t)BB*NN*CC], gG2[(size_t)BB*NN*CC];
__device__ __align__(256) __nv_bfloat16 gH0[(size_t)BB*NN*CC], gH1[(size_t)BB*NN*CC];
__device__ __align__(256) __nv_bfloat16 gP0[(size_t)BB*NN*NN], gP1[(size_t)BB*NN*NN];
__device__ __align__(256) uint32_t g_mw[(size_t)NN * (NN / 32)];
__device__ int   g_idx[BB * NN];
__device__ float g_mean[2 * BB * CC];
__device__ float g_istd[2 * BB * CC];

__device__ __forceinline__ float int_or_float(int v) {
    return (v >= -100000 && v <= 100000) ? (float)v : __int_as_float(v);
}
__device__ __forceinline__ int idx8(int base4, int k) {
    return (k < 4) ? (base4 + k) : (64 + base4 + (k - 4));
}
__device__ __forceinline__ void split3(float v, __nv_bfloat16& h, __nv_bfloat16& m,
                                       __nv_bfloat16& l) {
    h = __float2bfloat16(v);
    float r1 = v - __bfloat162float(h);
    m = __float2bfloat16(r1);
    l = __float2bfloat16(r1 - __bfloat162float(m));
}
__device__ __forceinline__ void mm_tile(const float (&As)[8][128], const float (&Bs)[8][128],
                                        int row4, int col4, float (&acc)[8][8]) {
#pragma unroll
    for (int kk = 0; kk < 8; ++kk) {
        float a[8], b[8];
#pragma unroll
        for (int i = 0; i < 4; ++i) { a[i] = As[kk][row4 + i]; a[4 + i] = As[kk][64 + row4 + i]; }
#pragma unroll
        for (int j = 0; j < 4; ++j) { b[j] = Bs[kk][col4 + j]; b[4 + j] = Bs[kk][64 + col4 + j]; }
#pragma unroll
        for (int i = 0; i < 8; ++i)
#pragma unroll
            for (int j = 0; j < 8; ++j) acc[i][j] += a[i] * b[j];
    }
}

// ======================= stats ================================================
__global__ void __launch_bounds__(256) stats_kernel(const float* __restrict__ x,
                                                    float* __restrict__ meanv,
                                                    float* __restrict__ istdv) {
    int row = blockIdx.x;
    const float* p = x + (size_t)row * NN;
    int t = threadIdx.x;
    float s = 0.f, s2 = 0.f;
    for (int i = t; i < NN; i += 256) { float v = p[i]; s += v; s2 += v * v; }
    __shared__ float sh1[256], sh2[256];
    sh1[t] = s; sh2[t] = s2; __syncthreads();
    for (int o = 128; o > 0; o >>= 1) {
        if (t < o) { sh1[t] += sh1[t + o]; sh2[t] += sh2[t + o]; }
        __syncthreads();
    }
    if (t == 0) {
        float m = sh1[0] / NN;
        float var = (sh2[0] - (float)NN * m * m) / (float)(NN - 1);
        meanv[row] = m;
        istdv[row] = rsqrtf(var + 1e-5f);
    }
}

// ======================= maskpack =============================================
__global__ void __launch_bounds__(256) maskpack_kernel(const float* __restrict__ m,
                                                       uint32_t* __restrict__ w) {
    int word = blockIdx.x * 256 + threadIdx.x;
    const float* p = m + (size_t)word * 32;
    uint32_t bits = 0;
#pragma unroll
    for (int k = 0; k < 32; ++k) bits |= (p[k] >= 0.5f ? 1u : 0u) << k;
    w[word] = bits;
}

// ======================= FGH GEMM (fp32 SIMT + optional bf16 splits) ==========
__global__ void __launch_bounds__(256) gemm_fgh(const float* __restrict__ x,
                                                const float* __restrict__ W,
                                                const float* __restrict__ bias,
                                                const float* __restrict__ meanv,
                                                const float* __restrict__ istdv,
                                                float* __restrict__ outF,
                                                __nv_bfloat16* __restrict__ o0,
                                                __nv_bfloat16* __restrict__ o1,
                                                __nv_bfloat16* __restrict__ o2,
                                                int use_norm) {
    const int b = blockIdx.z, n0 = blockIdx.x * 128, c0 = blockIdx.y * 128;
    __shared__ float As[8][128], Bs[8][128];
    const int t = threadIdx.x, tx = t & 15, ty = t >> 4;
    const int row4 = ty * 4, col4 = tx * 4;
    const int ai = t & 127, ak0 = t >> 7;
    const int lr = t >> 1, lq = (t & 1) * 4;
    const float* xb = x + (size_t)b * CC * NN;
    const float* mb = meanv + b * CC;
    const float* ib = istdv + b * CC;
    float acc[8][8];
#pragma unroll
    for (int i = 0; i < 8; ++i)
#pragma unroll
        for (int j = 0; j < 8; ++j) acc[i][j] = 0.f;
    for (int k0 = 0; k0 < CC; k0 += 8) {
#pragma unroll
        for (int u = 0; u < 4; ++u) {
            int kk = ak0 + 2 * u;
            float v = xb[(size_t)(k0 + kk) * NN + n0 + ai];
            if (use_norm) v = (v - mb[k0 + kk]) * ib[k0 + kk];
            As[kk][ai] = v;
        }
        float4 wv = *(const float4*)(W + (size_t)(c0 + lr) * CC + k0 + lq);
        Bs[lq + 0][lr] = wv.x; Bs[lq + 1][lr] = wv.y; Bs[lq + 2][lr] = wv.z; Bs[lq + 3][lr] = wv.w;
        __syncthreads();
        mm_tile(As, Bs, row4, col4, acc);
        __syncthreads();
    }
#pragma unroll
    for (int i = 0; i < 8; ++i) {
        int n = n0 + idx8(row4, i);
        size_t ob = ((size_t)b * NN + n) * CC + c0;
#pragma unroll
        for (int j = 0; j < 8; ++j) {
            int cj = idx8(col4, j);
            float v = acc[i][j] + bias[c0 + cj];
            if (outF) outF[ob + cj] = v;
            if (o0) {
                __nv_bfloat16 h, m, l; split3(v, h, m, l);
                o0[ob + cj] = h; o1[ob + cj] = m; o2[ob + cj] = l;
            }
        }
    }
}

// ======================= H transpose + 2-split: [n][c] -> [c][n] ==============
__global__ void __launch_bounds__(256) tsplitH_kernel(const float* __restrict__ in,
                                                      __nv_bfloat16* __restrict__ o0,
                                                      __nv_bfloat16* __restrict__ o1) {
    __shared__ float tile[32][33];
    int b = blockIdx.z, c0 = blockIdx.x * 32, n0 = blockIdx.y * 32;
    int tx = threadIdx.x & 31, ty = threadIdx.x >> 5;
    const float* ip = in + (size_t)b * NN * CC;
#pragma unroll
    for (int j = 0; j < 32; j += 8)
        tile[ty + j][tx] = ip[(size_t)(n0 + ty + j) * CC + c0 + tx];
    __syncthreads();
    size_t ob = (size_t)b * NN * CC;
#pragma unroll
    for (int j = 0; j < 32; j += 8) {
        float v = tile[tx][ty + j];
        __nv_bfloat16 h = __float2bfloat16(v);
        size_t o = ob + (size_t)(c0 + ty + j) * NN + n0 + tx;
        o0[o] = h;
        o1[o] = __float2bfloat16(v - __bfloat162float(h));
    }
}

// ======================= mma.sync split-bf16 GEMM =============================
// out[b, row0+r, col0+c] = sum over NPAIR level pairs of A[r][k]*B[c][k]
// smem stage: A 128x64 bf16 (stride 72) + B 128x64 (stride 72); 2 stages.
#define TCPAD 72
#define TCROWB (TCPAD * 2)          // 144 bytes/row
#define TCMAT (128 * TCROWB)        // 18432
#define TCSTG (2 * TCMAT)           // 36864 per stage
template<int LEV, int NPAIR>
__global__ void __launch_bounds__(256, 1) gemm_tc(
    const __nv_bfloat16* __restrict__ A0, const __nv_bfloat16* __restrict__ A1,
    const __nv_bfloat16* __restrict__ A2,
    const __nv_bfloat16* __restrict__ B0, const __nv_bfloat16* __restrict__ B1,
    const __nv_bfloat16* __restrict__ B2,
    int K, long aB, long bB, float* __restrict__ out, int ldo, long oB) {
    extern __shared__ char smem[];
    const uint32_t sb = smem_u32(smem);
    const int tid = threadIdx.x, lane = tid & 31, wid = tid >> 5;
    const int b = blockIdx.z, row0 = blockIdx.y * 128, col0 = blockIdx.x * 128;
    const int wm = (wid >> 1) * 32, wn = (wid & 1) * 64;

    const __nv_bfloat16* Ap[3] = {A0 + (size_t)b * aB, A1 + (size_t)b * aB, A2 + (size_t)b * aB};
    const __nv_bfloat16* Bp[3] = {B0 + (size_t)b * bB, B1 + (size_t)b * bB, B2 + (size_t)b * bB};
    const int PA[6] = {0, 0, 1, 0, 2, 1};
    const int PB[6] = {0, 1, 0, 2, 0, 1};

    const int KC = K >> 6;              // chunks per pair
    const int nCh = KC * NPAIR;
    const int lrow = tid >> 3, lseg = tid & 7;   // loader: 32 rows per 256thr pass

    float acc[2][8][4];
#pragma unroll
    for (int i = 0; i < 2; ++i)
#pragma unroll
        for (int j = 0; j < 8; ++j)
#pragma unroll
            for (int q = 0; q < 4; ++q) acc[i][j][q] = 0.f;

    auto load_chunk = [&](int ch, int st) {
        int p = ch / KC, c = ch - p * KC;
        const __nv_bfloat16* Asrc = Ap[PA[NPAIR == 3 ? p : p + 3] - (NPAIR == 3 ? PA[3] * 0 : 0)];
        // (avoid fancy indexing; recompute below)
        Asrc = Ap[(NPAIR == 3) ? PA[p] : PA[p]];
        const __nv_bfloat16* Bsrc = Bp[(NPAIR == 3) ? PB[p] : PB[p]];
        int k0 = c << 6;
        uint32_t sA = sb + st * TCSTG;
        uint32_t sB = sA + TCMAT;
#pragma unroll
        for (int i = 0; i < 4; ++i) {
            int row = lrow + i * 32;
            cp_async16(sA + row * TCROWB + lseg * 16,
                       Asrc + (size_t)(row0 + row) * K + k0 + lseg * 8);
            cp_async16(sB + row * TCROWB + lseg * 16,
                       Bsrc + (size_t)(col0 + row) * K + k0 + lseg * 8);
        }
        CP_COMMIT();
    };

    load_chunk(0, 0);
    for (int ch = 0; ch < nCh; ++ch) {
        const int st = ch & 1;
        if (ch + 1 < nCh) { load_chunk(ch + 1, st ^ 1); CP_WAIT(1); }
        else              { CP_WAIT(0); }
        __syncthreads();
        const uint32_t sA = sb + st * TCSTG;
        const uint32_t sB = sA + TCMAT;
        const int lr16 = lane & 15, lk8 = (lane >> 4) * 8;
#pragma unroll
        for (int ks = 0; ks < 4; ++ks) {
            uint32_t a[2][4], bf[4][4];
#pragma unroll
            for (int mf = 0; mf < 2; ++mf)
                ldmx4(a[mf][0], a[mf][1], a[mf][2], a[mf][3],
                      sA + (wm + mf * 16 + lr16) * TCROWB + (ks * 16 + lk8) * 2);
#pragma unroll
            for (int nb = 0; nb < 4; ++nb)
                ldmx4(bf[nb][0], bf[nb][1], bf[nb][2], bf[nb][3],
                      sB + (wn + nb * 16 + lr16) * TCROWB + (ks * 16 + lk8) * 2);
#pragma unroll
            for (int mf = 0; mf < 2; ++mf)
#pragma unroll
                for (int nf = 0; nf < 8; ++nf) {
                    int nb = nf >> 1, hi = nf & 1;
                    mma_bf16(acc[mf][nf], a[mf], bf[nb][hi], bf[nb][hi + 2]);
                }
        }
        __syncthreads();
    }

    // epilogue: direct fp32 stores (float2 per frag row)
    const int r4 = lane >> 2, c2 = (lane & 3) * 2;
#pragma unroll
    for (int mf = 0; mf < 2; ++mf)
#pragma unroll
        for (int nf = 0; nf < 8; ++nf) {
            int row = row0 + wm + mf * 16 + r4;
            int col = col0 + wn + nf * 8 + c2;
            float* d0 = out + (size_t)b * oB + (size_t)row * ldo + col;
            *(float2*)d0 = make_float2(acc[mf][nf][0], acc[mf][nf][1]);
            float* d1 = d0 + 8 * ldo;
            *(float2*)d1 = make_float2(acc[mf][nf][2], acc[mf][nf][3]);
        }
}

// ======================= masked softmax -> bf16 split probs ===================
__global__ void __launch_bounds__(256) softmax_kernel(const float* __restrict__ S,
                                                      const uint32_t* __restrict__ mw,
                                                      __nv_bfloat16* __restrict__ P0,
                                                      __nv_bfloat16* __restrict__ P1) {
    const int bn = blockIdx.x, n = bn & (NN - 1);
    const float* row = S + (size_t)bn * NN;
    const uint32_t* mword = mw + (size_t)n * (NN / 32);
    const int t = threadIdx.x;
    float v[16];
    float mx = NEGBIG;
#pragma unroll
    for (int r = 0; r < 16; ++r) {
        int i = t + r * 256;
        uint32_t bit = (mword[i >> 5] >> (i & 31)) & 1u;
        v[r] = bit ? row[i] : NEGBIG;
        mx = fmaxf(mx, v[r]);
    }
    __shared__ float red[256];
    red[t] = mx; __syncthreads();
    for (int o = 128; o > 0; o >>= 1) { if (t < o) red[t] = fmaxf(red[t], red[t + o]); __syncthreads(); }
    mx = red[0]; __syncthreads();
    float sum = 0.f;
#pragma unroll
    for (int r = 0; r < 16; ++r) {
        float e = (v[r] > -1e37f) ? expf(v[r] - mx) : 0.f;
        v[r] = e; sum += e;
    }
    red[t] = sum; __syncthreads();
    for (int o = 128; o > 0; o >>= 1) { if (t < o) red[t] += red[t + o]; __syncthreads(); }
    float inv = 1.f / red[0];
    __nv_bfloat16* p0 = P0 + (size_t)bn * NN;
    __nv_bfloat16* p1 = P1 + (size_t)bn * NN;
#pragma unroll
    for (int r = 0; r < 16; ++r) {
        int i = t + r * 256;
        float p = v[r] * inv;
        __nv_bfloat16 h = __float2bfloat16(p);
        p0[i] = h;
        p1[i] = __float2bfloat16(p - __bfloat162float(h));
    }
}

// ======================= masked argmax ========================================
__global__ void __launch_bounds__(256) argmax_kernel(const float* __restrict__ S,
                                                     const uint32_t* __restrict__ mw,
                                                     int* __restrict__ idxv) {
    const int bn = blockIdx.x, n = bn & (NN - 1);
    const float* row = S + (size_t)bn * NN;
    const uint32_t* mword = mw + (size_t)n * (NN / 32);
    const int t = threadIdx.x;
    float best = -INFINITY; int bi = 0;
#pragma unroll
    for (int r = 0; r < 16; ++r) {
        int i = t + r * 256;
        uint32_t bit = (mword[i >> 5] >> (i & 31)) & 1u;
        float sv = bit ? row[i] : NEGBIG;
        if (sv > best) { best = sv; bi = i; }
    }
    __shared__ float rv[256];
    __shared__ int   ri[256];
    rv[t] = best; ri[t] = bi; __syncthreads();
    for (int o = 128; o > 0; o >>= 1) {
        if (t < o) {
            if (rv[t + o] > rv[t] || (rv[t + o] == rv[t] && ri[t + o] < ri[t])) {
                rv[t] = rv[t + o]; ri[t] = ri[t + o];
            }
        }
        __syncthreads();
    }
    if (t == 0) idxv[bn] = ri[0];
}

// ======================= combine ==============================================
__global__ void __launch_bounds__(256) combine_kernel(const float* __restrict__ O,
                                                      const float* __restrict__ Hm,
                                                      const int* __restrict__ idxv,
                                                      const int* __restrict__ t1p,
                                                      const int* __restrict__ t2p,
                                                      float* __restrict__ V) {
    const int bn = blockIdx.x, b = bn >> 12;
    const float t1f = int_or_float(t1p[0]);
    const float t2f = int_or_float(t2p[0]);
    const int id = idxv[bn];
    const float* op = O + (size_t)bn * CC;
    const float* hp = Hm + ((size_t)b * NN + id) * CC;
    float* vp = V + (size_t)bn * CC;
    for (int c = threadIdx.x; c < CC; c += 256)
        vp[c] = t1f * op[c] + t2f * hp[c];
}

// ======================= final GEMM + residual ================================
__global__ void __launch_bounds__(256) gemm_final(const float* __restrict__ Wo,
                                                  const float* __restrict__ V,
                                                  const float* __restrict__ bo,
                                                  const float* __restrict__ content,
                                                  const int* __restrict__ t1p,
                                                  const int* __restrict__ t2p,
                                                  float* __restrict__ out) {
    const int b = blockIdx.z, n0 = blockIdx.x * 128, c0 = blockIdx.y * 128;
    __shared__ float As[8][128], Bs[8][128];
    const int t = threadIdx.x, tx = t & 15, ty = t >> 4;
    const int row4 = ty * 4, col4 = tx * 4;
    const int lr = t >> 1, lq = (t & 1) * 4;
    const float* Vb = V + (size_t)b * NN * CC;
    float acc[8][8];
#pragma unroll
    for (int i = 0; i < 8; ++i)
#pragma unroll
        for (int j = 0; j < 8; ++j) acc[i][j] = 0.f;
    for (int k0 = 0; k0 < CC; k0 += 8) {
        float4 av = *(const float4*)(Wo + (size_t)(c0 + lr) * CC + k0 + lq);
        float4 bv = *(const float4*)(Vb + (size_t)(n0 + lr) * CC + k0 + lq);
        As[lq + 0][lr] = av.x; As[lq + 1][lr] = av.y; As[lq + 2][lr] = av.z; As[lq + 3][lr] = av.w;
        Bs[lq + 0][lr] = bv.x; Bs[lq + 1][lr] = bv.y; Bs[lq + 2][lr] = bv.z; Bs[lq + 3][lr] = bv.w;
        __syncthreads();
        mm_tile(As, Bs, row4, col4, acc);
        __syncthreads();
    }
    const float t12 = int_or_float(t1p[0]) + int_or_float(t2p[0]);
#pragma unroll
    for (int i = 0; i < 8; ++i) {
        int c = c0 + idx8(row4, i);
        float bb = t12 * bo[c];
        float* op = out + ((size_t)b * CC + c) * NN + n0;
        const float* cp = content + ((size_t)b * CC + c) * NN + n0;
        float4 c0v = *(const float4*)(cp + col4);
        float4 c1v = *(const float4*)(cp + 64 + col4);
        *(float4*)(op + col4) = make_float4(acc[i][0] + bb + c0v.x, acc[i][1] + bb + c0v.y,
                                            acc[i][2] + bb + c0v.z, acc[i][3] + bb + c0v.w);
        *(float4*)(op + 64 + col4) = make_float4(acc[i][4] + bb + c1v.x, acc[i][5] + bb + c1v.y,
                                                 acc[i][6] + bb + c1v.z, acc[i][7] + bb + c1v.w);
    }
}

// ======================= launch ===============================================
extern "C" void kernel_launch(void* const* d_in, const int* in_sizes, int n_in,
                              void* d_out, int out_size) {
    (void)in_sizes; (void)n_in; (void)out_size;
    const float* content     = (const float*)d_in[0];
    const float* style       = (const float*)d_in[1];
    const float* content_sem = (const float*)d_in[2];
    const float* style_sem   = (const float*)d_in[3];
    const float* map64       = (const float*)d_in[5];
    const int*   t1p = (const int*)d_in[6];
    const int*   t2p = (const int*)d_in[7];
    const float* Wf = (const float*)d_in[8];   const float* bf = (const float*)d_in[9];
    const float* Wg = (const float*)d_in[10];  const float* bg = (const float*)d_in[11];
    const float* Wh = (const float*)d_in[12];  const float* bh = (const float*)d_in[13];
    const float* Wo = (const float*)d_in[14];  const float* bo = (const float*)d_in[15];
    float* out = (float*)d_out;

    float *pS, *pH, *pO, *pMean, *pIstd; int* pIdx; uint32_t* pMW;
    __nv_bfloat16 *pF0, *pF1, *pF2, *pG0, *pG1, *pG2, *pH0, *pH1, *pP0, *pP1;
    cudaGetSymbolAddress((void**)&pS, g_S);
    cudaGetSymbolAddress((void**)&pH, g_H);
    cudaGetSymbolAddress((void**)&pO, g_O);
    cudaGetSymbolAddress((void**)&pMean, g_mean);
    cudaGetSymbolAddress((void**)&pIstd, g_istd);
    cudaGetSymbolAddress((void**)&pIdx, g_idx);
    cudaGetSymbolAddress((void**)&pMW, g_mw);
    cudaGetSymbolAddress((void**)&pF0, gF0); cudaGetSymbolAddress((void**)&pF1, gF1);
    cudaGetSymbolAddress((void**)&pF2, gF2);
    cudaGetSymbolAddress((void**)&pG0, gG0); cudaGetSymbolAddress((void**)&pG1, gG1);
    cudaGetSymbolAddress((void**)&pG2, gG2);
    cudaGetSymbolAddress((void**)&pH0, gH0); cudaGetSymbolAddress((void**)&pH1, gH1);
    cudaGetSymbolAddress((void**)&pP0, gP0); cudaGetSymbolAddress((void**)&pP1, gP1);

    const int SMTC = 2 * TCSTG;   // 73728 bytes dynamic smem
    cudaFuncSetAttribute(gemm_tc<2, 3>, cudaFuncAttributeMaxDynamicSharedMemorySize, SMTC);
    cudaFuncSetAttribute(gemm_tc<3, 6>, cudaFuncAttributeMaxDynamicSharedMemorySize, SMTC);

    const dim3 gFGH(NN / 128, CC / 128, BB);
    const dim3 gSC(NN / 128, NN / 128, BB);
    const dim3 gAV(CC / 128, NN / 128, BB);
    const long FCB = (long)NN * CC, SNB = (long)NN * NN;

    maskpack_kernel<<<(NN * (NN / 32)) / 256, 256>>>(map64, pMW);

    // ---- SCA (semantic, soft) ----
    stats_kernel<<<BB * CC, 256>>>(content_sem, pMean, pIstd);
    stats_kernel<<<BB * CC, 256>>>(style_sem, pMean + BB * CC, pIstd + BB * CC);
    gemm_fgh<<<gFGH, 256>>>(content_sem, Wf, bf, pMean, pIstd, nullptr, pF0, pF1, pF2, 1);
    gemm_fgh<<<gFGH, 256>>>(style_sem, Wg, bg, pMean + BB * CC, pIstd + BB * CC, nullptr, pG0, pG1, pG2, 1);
    gemm_fgh<<<gFGH, 256>>>(style, Wh, bh, pMean, pIstd, pH, nullptr, nullptr, nullptr, 0);
    tsplitH_kernel<<<dim3(CC / 32, NN / 32, BB), 256>>>(pH, pH0, pH1);
    gemm_tc<2, 3><<<gSC, 256, SMTC>>>(pF0, pF1, pF1, pG0, pG1, pG1, CC, FCB, FCB, pS, NN, SNB);
    softmax_kernel<<<BB * NN, 256>>>(pS, pMW, pP0, pP1);
    gemm_tc<2, 3><<<gAV, 256, SMTC>>>(pP0, pP1, pP1, pH0, pH1, pH1, NN, SNB, FCB, pO, CC, FCB);

    // ---- SSA (content/style, hard argmax == gather) ----
    stats_kernel<<<BB * CC, 256>>>(content, pMean, pIstd);
    stats_kernel<<<BB * CC, 256>>>(style, pMean + BB * CC, pIstd + BB * CC);
    gemm_fgh<<<gFGH, 256>>>(content, Wf, bf, pMean, pIstd, nullptr, pF0, pF1, pF2, 1);
    gemm_fgh<<<gFGH, 256>>>(style, Wg, bg, pMean + BB * CC, pIstd + BB * CC, nullptr, pG0, pG1, pG2, 1);
    gemm_tc<3, 6><<<gSC, 256, SMTC>>>(pF0, pF1, pF2, pG0, pG1, pG2, CC, FCB, FCB, pS, NN, SNB);
    argmax_kernel<<<BB * NN, 256>>>(pS, pMW, pIdx);

    // ---- combine + output conv + residual ----
    combine_kernel<<<BB * NN, 256>>>(pO, pH, pIdx, t1p, t2p, pS);   // V -> g_S (reuse)
    gemm_final<<<gFGH, 256>>>(Wo, pS, bo, content, t1p, t2p, out);
}

// round 5
// speedup vs baseline: 1.8150x; 1.1845x over previous
#include <cuda_runtime.h>
#include <cuda_bf16.h>
#include <cstdint>

#define BB 2
#define CC 256
#define NN 4096
#define NEGBIG (-3.4028234e38f)

// ======================= PTX helpers (compute_103-legal) ======================
__device__ __forceinline__ uint32_t smem_u32(const void* p) {
    uint32_t a;
    asm("{ .reg .u64 t; cvta.to.shared.u64 t, %1; cvt.u32.u64 %0, t; }" : "=r"(a) : "l"(p));
    return a;
}
__device__ __forceinline__ void cp_async16(uint32_t s, const void* g) {
    asm volatile("cp.async.ca.shared.global [%0], [%1], 16;" :: "r"(s), "l"(g));
}
#define CP_COMMIT() asm volatile("cp.async.commit_group;" ::: "memory")
#define CP_WAIT(n)  asm volatile("cp.async.wait_group %0;" :: "n"(n) : "memory")
__device__ __forceinline__ void ldmx4(uint32_t& r0, uint32_t& r1, uint32_t& r2,
                                      uint32_t& r3, uint32_t a) {
    asm volatile("ldmatrix.sync.aligned.m8n8.x4.shared.b16 {%0,%1,%2,%3}, [%4];"
                 : "=r"(r0), "=r"(r1), "=r"(r2), "=r"(r3) : "r"(a));
}
__device__ __forceinline__ void mma_bf16(float* c, const uint32_t* a, uint32_t b0,
                                         uint32_t b1) {
    asm volatile("mma.sync.aligned.m16n8k16.row.col.f32.bf16.bf16.f32 "
                 "{%0,%1,%2,%3}, {%4,%5,%6,%7}, {%8,%9}, {%0,%1,%2,%3};"
                 : "+f"(c[0]), "+f"(c[1]), "+f"(c[2]), "+f"(c[3])
                 : "r"(a[0]), "r"(a[1]), "r"(a[2]), "r"(a[3]), "r"(b0), "r"(b1));
}

// ======================= scratch ==============================================
#define SZF ((size_t)BB * NN * CC)          // per (batch,feature) elems
__device__ __align__(256) float g_S[(size_t)BB * NN * NN];
__device__ __align__(256) float g_Opart[(size_t)4 * SZF];
__device__ __align__(256) __nv_bfloat16 g_T[(size_t)15 * SZF];    // 5 tensors x 3 levels, [b][n][c]
__device__ __align__(256) __nv_bfloat16 g_PJ[(size_t)15 * SZF];   // 5 proj outputs x 3 levels
__device__ __align__(256) __nv_bfloat16 g_Ht0[SZF], g_Ht1[SZF];   // H^T 2-level [b][c][n]
__device__ __align__(256) __nv_bfloat16 g_P0[(size_t)BB * NN * NN], g_P1[(size_t)BB * NN * NN];
__device__ __align__(256) __nv_bfloat16 g_V0[SZF], g_V1[SZF];
__device__ __align__(256) __nv_bfloat16 g_W[(size_t)12 * CC * CC]; // 4 weights x 3 levels
__device__ __align__(256) uint32_t g_mw[(size_t)NN * (NN / 32)];
__device__ int   g_idx[BB * NN];
__device__ float g_mean[4 * BB * CC];
__device__ float g_istd[4 * BB * CC];

__device__ __forceinline__ float int_or_float(int v) {
    return (v >= -100000 && v <= 100000) ? (float)v : __int_as_float(v);
}
__device__ __forceinline__ void split3(float v, __nv_bfloat16& h, __nv_bfloat16& m,
                                       __nv_bfloat16& l) {
    h = __float2bfloat16(v);
    float r1 = v - __bfloat162float(h);
    m = __float2bfloat16(r1);
    l = __float2bfloat16(r1 - __bfloat162float(m));
}
__device__ __forceinline__ uint32_t packbf(__nv_bfloat16 a, __nv_bfloat16 b) {
    uint16_t lo = *(uint16_t*)&a, hi = *(uint16_t*)&b;
    return (uint32_t)lo | ((uint32_t)hi << 16);
}

// ======================= stats ================================================
__global__ void __launch_bounds__(256) stats_kernel(const float* __restrict__ x,
                                                    float* __restrict__ meanv,
                                                    float* __restrict__ istdv) {
    int row = blockIdx.x;
    const float* p = x + (size_t)row * NN;
    int t = threadIdx.x;
    float s = 0.f, s2 = 0.f;
    for (int i = t; i < NN; i += 256) { float v = p[i]; s += v; s2 += v * v; }
    __shared__ float sh1[256], sh2[256];
    sh1[t] = s; sh2[t] = s2; __syncthreads();
    for (int o = 128; o > 0; o >>= 1) {
        if (t < o) { sh1[t] += sh1[t + o]; sh2[t] += sh2[t + o]; }
        __syncthreads();
    }
    if (t == 0) {
        float m = sh1[0] / NN;
        float var = (sh2[0] - (float)NN * m * m) / (float)(NN - 1);
        meanv[row] = m;
        istdv[row] = rsqrtf(var + 1e-5f);
    }
}

// ======================= maskpack =============================================
__global__ void __launch_bounds__(256) maskpack_kernel(const float* __restrict__ m,
                                                       uint32_t* __restrict__ w) {
    int word = blockIdx.x * 256 + threadIdx.x;
    const float* p = m + (size_t)word * 32;
    uint32_t bits = 0;
#pragma unroll
    for (int k = 0; k < 32; ++k) bits |= (p[k] >= 0.5f ? 1u : 0u) << k;
    w[word] = bits;
}

// ======================= transpose + (norm) + 3-split: [b][C][N] -> [b][N][C] ==
__global__ void __launch_bounds__(256) tsplit_kernel(const float* __restrict__ in,
                                                     const float* __restrict__ mean,
                                                     const float* __restrict__ istd,
                                                     __nv_bfloat16* __restrict__ o0,
                                                     __nv_bfloat16* __restrict__ o1,
                                                     __nv_bfloat16* __restrict__ o2) {
    __shared__ float tile[32][33];
    int b = blockIdx.z;
    int n0 = blockIdx.x * 32, c0 = blockIdx.y * 32;
    int tx = threadIdx.x & 31, ty = threadIdx.x >> 5;
    const float* ip = in + (size_t)b * CC * NN;
#pragma unroll
    for (int j = 0; j < 32; j += 8) {
        int c = c0 + ty + j;
        float v = ip[(size_t)c * NN + n0 + tx];
        if (mean) v = (v - mean[b * CC + c]) * istd[b * CC + c];
        tile[ty + j][tx] = v;
    }
    __syncthreads();
    size_t ob = (size_t)b * NN * CC;
#pragma unroll
    for (int j = 0; j < 32; j += 8) {
        int n = n0 + ty + j;
        float v = tile[tx][ty + j];
        __nv_bfloat16 h, m, l; split3(v, h, m, l);
        size_t o = ob + (size_t)n * CC + c0 + tx;
        o0[o] = h; o1[o] = m; o2[o] = l;
    }
}

// ======================= weight 3-split =======================================
__global__ void __launch_bounds__(256) wsplit_kernel(const float* __restrict__ in,
                                                     __nv_bfloat16* __restrict__ o0,
                                                     __nv_bfloat16* __restrict__ o1,
                                                     __nv_bfloat16* __restrict__ o2) {
    int i = blockIdx.x * 256 + threadIdx.x;
    __nv_bfloat16 h, m, l; split3(in[i], h, m, l);
    o0[i] = h; o1[i] = m; o2[i] = l;
}

// ======================= tc core (512 thr, tile 128x256, K-chunk 64) ==========
#define TCROWB 144
#define STG_A (128 * TCROWB)
#define STG_B (256 * TCROWB)
#define STG_T (STG_A + STG_B)
#define NSTAGE 3
#define SMTC (NSTAGE * STG_T)

__device__ __forceinline__ void tc_load_chunk(uint32_t sb, int st, int tid,
                                              const __nv_bfloat16* Asrc,
                                              const __nv_bfloat16* Bsrc,
                                              int row0, int col0, int K, int k0) {
    uint32_t sA = sb + st * STG_T;
    uint32_t sB = sA + STG_A;
#pragma unroll
    for (int i = 0; i < 6; ++i) {
        int g = tid + i * 512;
        if (i < 2) {
            int row = g >> 3, seg = g & 7;
            cp_async16(sA + row * TCROWB + seg * 16,
                       Asrc + (size_t)(row0 + row) * K + k0 + seg * 8);
        } else {
            int gg = g - 1024;
            int row = gg >> 3, seg = gg & 7;
            cp_async16(sB + row * TCROWB + seg * 16,
                       Bsrc + (size_t)(col0 + row) * K + k0 + seg * 8);
        }
    }
    CP_COMMIT();
}

__device__ __forceinline__ void tc_compute(uint32_t sb, int st, int lane, int wm,
                                           int wn, float (&acc)[2][8][4]) {
    const uint32_t sA = sb + st * STG_T;
    const uint32_t sB = sA + STG_A;
    const int lr16 = lane & 15, lk8 = (lane >> 4) * 8;
#pragma unroll
    for (int ks = 0; ks < 4; ++ks) {
        uint32_t a[2][4], bf[4][4];
#pragma unroll
        for (int mf = 0; mf < 2; ++mf)
            ldmx4(a[mf][0], a[mf][1], a[mf][2], a[mf][3],
                  sA + (wm + mf * 16 + lr16) * TCROWB + (ks * 16 + lk8) * 2);
#pragma unroll
        for (int nb = 0; nb < 4; ++nb)
            ldmx4(bf[nb][0], bf[nb][1], bf[nb][2], bf[nb][3],
                  sB + (wn + nb * 16 + lr16) * TCROWB + (ks * 16 + lk8) * 2);
#pragma unroll
        for (int mf = 0; mf < 2; ++mf)
#pragma unroll
            for (int nf = 0; nf < 8; ++nf) {
                int nb = nf >> 1, hi = nf & 1;
                mma_bf16(acc[mf][nf], a[mf], bf[nb][hi], bf[nb][hi + 2]);
            }
    }
}

__constant__ int c_PA[6] = {0, 0, 1, 0, 2, 1};
__constant__ int c_PB[6] = {0, 1, 0, 2, 0, 1};

// ======================= generic tc GEMM ======================================
// out[row,col] = sum_pairs sum_k A_lev[row,k] * B_lev[col,k]
// EPI 0: fp32 store (+ K-split partial offset).  EPI 2: final (bias+content).
template<int NPAIR, int EPI, int KSPLIT>
__global__ void __launch_bounds__(512, 1) gemm_tc(
    const __nv_bfloat16* __restrict__ A0, const __nv_bfloat16* __restrict__ A1,
    const __nv_bfloat16* __restrict__ A2,
    const __nv_bfloat16* __restrict__ B0, const __nv_bfloat16* __restrict__ B1,
    const __nv_bfloat16* __restrict__ B2,
    int K, long aB, long bB,
    float* __restrict__ out, int ldo, long oB, long pB,
    const float* __restrict__ bias, const float* __restrict__ content,
    const int* __restrict__ t1p, const int* __restrict__ t2p) {
    extern __shared__ char smem[];
    const uint32_t sb = smem_u32(smem);
    const int tid = threadIdx.x, lane = tid & 31, wid = tid >> 5;
    const int wm = (wid & 3) * 32, wn = (wid >> 2) * 64;
    const int z = blockIdx.z, b = z / KSPLIT, ks = z % KSPLIT;
    const int kLen = K / KSPLIT, kOff = ks * kLen;
    const int row0 = blockIdx.y * 128, col0 = blockIdx.x * 256;
    const __nv_bfloat16* Ap[3] = {A0 + (size_t)b * aB, A1 + (size_t)b * aB, A2 + (size_t)b * aB};
    const __nv_bfloat16* Bp[3] = {B0 + (size_t)b * bB, B1 + (size_t)b * bB, B2 + (size_t)b * bB};
    const int KC = kLen >> 6, nCh = KC * NPAIR;

    float acc[2][8][4];
#pragma unroll
    for (int i = 0; i < 2; ++i)
#pragma unroll
        for (int j = 0; j < 8; ++j)
#pragma unroll
            for (int q = 0; q < 4; ++q) acc[i][j][q] = 0.f;

    auto load = [&](int ch) {
        int p = ch / KC, c = ch - p * KC;
        tc_load_chunk(sb, ch % NSTAGE, tid, Ap[c_PA[p]], Bp[c_PB[p]],
                      row0, col0, K, kOff + (c << 6));
    };
    load(0); load(1);
    for (int ch = 0; ch < nCh; ++ch) {
        if (ch + 2 < nCh) { load(ch + 2); CP_WAIT(2); }
        else if (ch + 1 < nCh) CP_WAIT(1);
        else CP_WAIT(0);
        __syncthreads();
        tc_compute(sb, ch % NSTAGE, lane, wm, wn, acc);
        __syncthreads();
    }

    const int r4 = lane >> 2, c2 = (lane & 3) * 2;
    float t12 = 0.f;
    if (EPI == 2) t12 = int_or_float(t1p[0]) + int_or_float(t2p[0]);
    float* ob = out + (size_t)b * oB + (size_t)ks * pB;
#pragma unroll
    for (int mf = 0; mf < 2; ++mf)
#pragma unroll
        for (int nf = 0; nf < 8; ++nf)
#pragma unroll
            for (int h = 0; h < 2; ++h) {
                int row = row0 + wm + mf * 16 + r4 + 8 * h;
                int col = col0 + wn + nf * 8 + c2;
                float v0 = acc[mf][nf][2 * h], v1 = acc[mf][nf][2 * h + 1];
                float* d = ob + (size_t)row * ldo + col;
                if (EPI == 2) {
                    float bb = t12 * bias[row];
                    const float* cp = content + (size_t)b * oB + (size_t)row * ldo + col;
                    v0 += bb + cp[0]; v1 += bb + cp[1];
                }
                *(float2*)d = make_float2(v0, v1);
            }
}

// ======================= batched projection GEMMs (5 jobs) ====================
struct FghArgs {
    const __nv_bfloat16* A[5][3];
    const __nv_bfloat16* W[5][3];
    const float* bias[5];
    __nv_bfloat16* O[5][3];
    int npair[5];
};
__global__ void __launch_bounds__(512, 1) gemm_fgh_tc(FghArgs args) {
    extern __shared__ char smem[];
    const uint32_t sb = smem_u32(smem);
    const int tid = threadIdx.x, lane = tid & 31, wid = tid >> 5;
    const int wm = (wid & 3) * 32, wn = (wid >> 2) * 64;
    const int z = blockIdx.z, job = z >> 1, b = z & 1;
    const int row0 = blockIdx.y * 128;
    const int KC = CC >> 6, nCh = KC * args.npair[job];
    const __nv_bfloat16* Ap[3];
    const __nv_bfloat16* Wp[3];
#pragma unroll
    for (int l = 0; l < 3; ++l) {
        Ap[l] = args.A[job][l] + (size_t)b * NN * CC;
        Wp[l] = args.W[job][l];
    }
    float acc[2][8][4];
#pragma unroll
    for (int i = 0; i < 2; ++i)
#pragma unroll
        for (int j = 0; j < 8; ++j)
#pragma unroll
            for (int q = 0; q < 4; ++q) acc[i][j][q] = 0.f;

    auto load = [&](int ch) {
        int p = ch / KC, c = ch - p * KC;
        tc_load_chunk(sb, ch % NSTAGE, tid, Ap[c_PA[p]], Wp[c_PB[p]],
                      row0, 0, CC, c << 6);
    };
    load(0); load(1);
    for (int ch = 0; ch < nCh; ++ch) {
        if (ch + 2 < nCh) { load(ch + 2); CP_WAIT(2); }
        else if (ch + 1 < nCh) CP_WAIT(1);
        else CP_WAIT(0);
        __syncthreads();
        tc_compute(sb, ch % NSTAGE, lane, wm, wn, acc);
        __syncthreads();
    }

    const int r4 = lane >> 2, c2 = (lane & 3) * 2;
    const float* bias = args.bias[job];
    size_t base = (size_t)b * NN * CC;
#pragma unroll
    for (int mf = 0; mf < 2; ++mf)
#pragma unroll
        for (int nf = 0; nf < 8; ++nf)
#pragma unroll
            for (int h = 0; h < 2; ++h) {
                int row = row0 + wm + mf * 16 + r4 + 8 * h;
                int col = wn + nf * 8 + c2;
                float v0 = acc[mf][nf][2 * h] + bias[col];
                float v1 = acc[mf][nf][2 * h + 1] + bias[col + 1];
                __nv_bfloat16 h0, m0, l0, h1, m1, l1;
                split3(v0, h0, m0, l0); split3(v1, h1, m1, l1);
                size_t off = base + (size_t)row * CC + col;
                *(uint32_t*)(args.O[job][0] + off) = packbf(h0, h1);
                *(uint32_t*)(args.O[job][1] + off) = packbf(m0, m1);
                *(uint32_t*)(args.O[job][2] + off) = packbf(l0, l1);
            }
}

// ======================= H transpose (from splits) + 2-split ==================
__global__ void __launch_bounds__(256) tsplitH_kernel(const __nv_bfloat16* __restrict__ H0,
                                                      const __nv_bfloat16* __restrict__ H1,
                                                      const __nv_bfloat16* __restrict__ H2,
                                                      __nv_bfloat16* __restrict__ o0,
                                                      __nv_bfloat16* __restrict__ o1) {
    __shared__ float tile[32][33];
    int b = blockIdx.z, c0 = blockIdx.x * 32, n0 = blockIdx.y * 32;
    int tx = threadIdx.x & 31, ty = threadIdx.x >> 5;
    size_t base = (size_t)b * NN * CC;
#pragma unroll
    for (int j = 0; j < 32; j += 8) {
        size_t o = base + (size_t)(n0 + ty + j) * CC + c0 + tx;
        tile[ty + j][tx] = __bfloat162float(H0[o]) + __bfloat162float(H1[o])
                         + __bfloat162float(H2[o]);
    }
    __syncthreads();
#pragma unroll
    for (int j = 0; j < 32; j += 8) {
        float v = tile[tx][ty + j];
        __nv_bfloat16 h = __float2bfloat16(v);
        size_t o = base + (size_t)(c0 + ty + j) * NN + n0 + tx;
        o0[o] = h;
        o1[o] = __float2bfloat16(v - __bfloat162float(h));
    }
}

// ======================= masked softmax -> bf16 split probs ===================
__global__ void __launch_bounds__(256) softmax_kernel(const float* __restrict__ S,
                                                      const uint32_t* __restrict__ mw,
                                                      __nv_bfloat16* __restrict__ P0,
                                                      __nv_bfloat16* __restrict__ P1) {
    const int bn = blockIdx.x, n = bn & (NN - 1);
    const float* row = S + (size_t)bn * NN;
    const uint32_t* mword = mw + (size_t)n * (NN / 32);
    const int t = threadIdx.x;
    float v[16];
    float mx = NEGBIG;
#pragma unroll
    for (int r = 0; r < 16; ++r) {
        int i = t + r * 256;
        uint32_t bit = (mword[i >> 5] >> (i & 31)) & 1u;
        v[r] = bit ? row[i] : NEGBIG;
        mx = fmaxf(mx, v[r]);
    }
    __shared__ float red[256];
    red[t] = mx; __syncthreads();
    for (int o = 128; o > 0; o >>= 1) { if (t < o) red[t] = fmaxf(red[t], red[t + o]); __syncthreads(); }
    mx = red[0]; __syncthreads();
    float sum = 0.f;
#pragma unroll
    for (int r = 0; r < 16; ++r) {
        float e = (v[r] > -1e37f) ? expf(v[r] - mx) : 0.f;
        v[r] = e; sum += e;
    }
    red[t] = sum; __syncthreads();
    for (int o = 128; o > 0; o >>= 1) { if (t < o) red[t] += red[t + o]; __syncthreads(); }
    float inv = 1.f / red[0];
    __nv_bfloat16* p0 = P0 + (size_t)bn * NN;
    __nv_bfloat16* p1 = P1 + (size_t)bn * NN;
#pragma unroll
    for (int r = 0; r < 16; ++r) {
        int i = t + r * 256;
        float p = v[r] * inv;
        __nv_bfloat16 h = __float2bfloat16(p);
        p0[i] = h;
        p1[i] = __float2bfloat16(p - __bfloat162float(h));
    }
}

// ======================= masked argmax ========================================
__global__ void __launch_bounds__(256) argmax_kernel(const float* __restrict__ S,
                                                     const uint32_t* __restrict__ mw,
                                                     int* __restrict__ idxv) {
    const int bn = blockIdx.x, n = bn & (NN - 1);
    const float* row = S + (size_t)bn * NN;
    const uint32_t* mword = mw + (size_t)n * (NN / 32);
    const int t = threadIdx.x;
    float best = -INFINITY; int bi = 0;
#pragma unroll
    for (int r = 0; r < 16; ++r) {
        int i = t + r * 256;
        uint32_t bit = (mword[i >> 5] >> (i & 31)) & 1u;
        float sv = bit ? row[i] : NEGBIG;
        if (sv > best) { best = sv; bi = i; }
    }
    __shared__ float rv[256];
    __shared__ int   ri[256];
    rv[t] = best; ri[t] = bi; __syncthreads();
    for (int o = 128; o > 0; o >>= 1) {
        if (t < o) {
            if (rv[t + o] > rv[t] || (rv[t + o] == rv[t] && ri[t + o] < ri[t])) {
                rv[t] = rv[t + o]; ri[t] = ri[t + o];
            }
        }
        __syncthreads();
    }
    if (t == 0) idxv[bn] = ri[0];
}

// ======================= combine (partials + gather -> V splits) ==============
__global__ void __launch_bounds__(256) combine_kernel(const float* __restrict__ Op,
                                                      const __nv_bfloat16* __restrict__ H0,
                                                      const __nv_bfloat16* __restrict__ H1,
                                                      const __nv_bfloat16* __restrict__ H2,
                                                      const int* __restrict__ idxv,
                                                      const int* __restrict__ t1p,
                                                      const int* __restrict__ t2p,
                                                      __nv_bfloat16* __restrict__ V0,
                                                      __nv_bfloat16* __restrict__ V1) {
    const int bn = blockIdx.x, b = bn >> 12;
    const float t1f = int_or_float(t1p[0]);
    const float t2f = int_or_float(t2p[0]);
    const int id = idxv[bn];
    const size_t ro = (size_t)bn * CC;
    const size_t hrow = (size_t)b * NN * CC + (size_t)id * CC;
    const int c = threadIdx.x;
    float o = Op[ro + c] + Op[SZF + ro + c] + Op[2 * SZF + ro + c] + Op[3 * SZF + ro + c];
    float h = __bfloat162float(H0[hrow + c]) + __bfloat162float(H1[hrow + c])
            + __bfloat162float(H2[hrow + c]);
    float v = t1f * o + t2f * h;
    __nv_bfloat16 vh = __float2bfloat16(v);
    V0[ro + c] = vh;
    V1[ro + c] = __float2bfloat16(v - __bfloat162float(vh));
}

// ======================= launch ===============================================
extern "C" void kernel_launch(void* const* d_in, const int* in_sizes, int n_in,
                              void* d_out, int out_size) {
    (void)in_sizes; (void)n_in; (void)out_size;
    const float* content     = (const float*)d_in[0];
    const float* style       = (const float*)d_in[1];
    const float* content_sem = (const float*)d_in[2];
    const float* style_sem   = (const float*)d_in[3];
    const float* map64       = (const float*)d_in[5];
    const int*   t1p = (const int*)d_in[6];
    const int*   t2p = (const int*)d_in[7];
    const float* Wf = (const float*)d_in[8];   const float* bf = (const float*)d_in[9];
    const float* Wg = (const float*)d_in[10];  const float* bg = (const float*)d_in[11];
    const float* Wh = (const float*)d_in[12];  const float* bh = (const float*)d_in[13];
    const float* Wo = (const float*)d_in[14];  const float* bo = (const float*)d_in[15];
    float* out = (float*)d_out;

    float *pS, *pOp, *pMean, *pIstd; int* pIdx; uint32_t* pMW;
    __nv_bfloat16 *pT, *pPJ, *pHt0, *pHt1, *pP0, *pP1, *pV0, *pV1, *pW;
    cudaGetSymbolAddress((void**)&pS, g_S);
    cudaGetSymbolAddress((void**)&pOp, g_Opart);
    cudaGetSymbolAddress((void**)&pT, g_T);
    cudaGetSymbolAddress((void**)&pPJ, g_PJ);
    cudaGetSymbolAddress((void**)&pHt0, g_Ht0);
    cudaGetSymbolAddress((void**)&pHt1, g_Ht1);
    cudaGetSymbolAddress((void**)&pP0, g_P0);
    cudaGetSymbolAddress((void**)&pP1, g_P1);
    cudaGetSymbolAddress((void**)&pV0, g_V0);
    cudaGetSymbolAddress((void**)&pV1, g_V1);
    cudaGetSymbolAddress((void**)&pW, g_W);
    cudaGetSymbolAddress((void**)&pMean, g_mean);
    cudaGetSymbolAddress((void**)&pIstd, g_istd);
    cudaGetSymbolAddress((void**)&pIdx, g_idx);
    cudaGetSymbolAddress((void**)&pMW, g_mw);

    cudaFuncSetAttribute(gemm_tc<3, 0, 1>, cudaFuncAttributeMaxDynamicSharedMemorySize, SMTC);
    cudaFuncSetAttribute(gemm_tc<6, 0, 1>, cudaFuncAttributeMaxDynamicSharedMemorySize, SMTC);
    cudaFuncSetAttribute(gemm_tc<3, 0, 4>, cudaFuncAttributeMaxDynamicSharedMemorySize, SMTC);
    cudaFuncSetAttribute(gemm_tc<3, 2, 1>, cudaFuncAttributeMaxDynamicSharedMemorySize, SMTC);
    cudaFuncSetAttribute(gemm_fgh_tc, cudaFuncAttributeMaxDynamicSharedMemorySize, SMTC);

    const long FCB = (long)NN * CC, SNB = (long)NN * NN, WCB = (long)CC * CC;
    auto T  = [&](int i, int l) { return pT + ((size_t)(i * 3 + l)) * SZF; };
    auto PJ = [&](int i, int l) { return pPJ + ((size_t)(i * 3 + l)) * SZF; };
    auto WL = [&](int m, int l) { return pW + ((size_t)(m * 3 + l)) * CC * CC; };

    maskpack_kernel<<<(NN * (NN / 32)) / 256, 256>>>(map64, pMW);

    // stats: content_sem(0), style_sem(1), content(2), style(3)
    stats_kernel<<<BB * CC, 256>>>(content_sem, pMean + 0 * BB * CC, pIstd + 0 * BB * CC);
    stats_kernel<<<BB * CC, 256>>>(style_sem,   pMean + 1 * BB * CC, pIstd + 1 * BB * CC);
    stats_kernel<<<BB * CC, 256>>>(content,     pMean + 2 * BB * CC, pIstd + 2 * BB * CC);
    stats_kernel<<<BB * CC, 256>>>(style,       pMean + 3 * BB * CC, pIstd + 3 * BB * CC);

    const dim3 gT32(NN / 32, CC / 32, BB);
    tsplit_kernel<<<gT32, 256>>>(content_sem, pMean + 0 * BB * CC, pIstd + 0 * BB * CC, T(0,0), T(0,1), T(0,2));
    tsplit_kernel<<<gT32, 256>>>(style_sem,   pMean + 1 * BB * CC, pIstd + 1 * BB * CC, T(1,0), T(1,1), T(1,2));
    tsplit_kernel<<<gT32, 256>>>(style,       nullptr, nullptr,                          T(2,0), T(2,1), T(2,2));
    tsplit_kernel<<<gT32, 256>>>(content,     pMean + 2 * BB * CC, pIstd + 2 * BB * CC, T(3,0), T(3,1), T(3,2));
    tsplit_kernel<<<gT32, 256>>>(style,       pMean + 3 * BB * CC, pIstd + 3 * BB * CC, T(4,0), T(4,1), T(4,2));

    wsplit_kernel<<<CC * CC / 256, 256>>>(Wf, WL(0,0), WL(0,1), WL(0,2));
    wsplit_kernel<<<CC * CC / 256, 256>>>(Wg, WL(1,0), WL(1,1), WL(1,2));
    wsplit_kernel<<<CC * CC / 256, 256>>>(Wh, WL(2,0), WL(2,1), WL(2,2));
    wsplit_kernel<<<CC * CC / 256, 256>>>(Wo, WL(3,0), WL(3,1), WL(3,2));

    // batched projections: j0 F_sca, j1 G_sca, j2 H, j3 F_ssa, j4 G_ssa
    FghArgs fa;
    const int jm[5] = {0, 1, 2, 0, 1};            // weight matrix per job
    const float* jb[5] = {bf, bg, bh, bf, bg};
    const int jnp[5] = {3, 3, 3, 6, 6};
    for (int j = 0; j < 5; ++j) {
        for (int l = 0; l < 3; ++l) {
            fa.A[j][l] = T(j, l);
            fa.W[j][l] = WL(jm[j], l);
            fa.O[j][l] = PJ(j, l);
        }
        fa.bias[j] = jb[j];
        fa.npair[j] = jnp[j];
    }
    gemm_fgh_tc<<<dim3(1, NN / 128, 10), 512, SMTC>>>(fa);

    tsplitH_kernel<<<dim3(CC / 32, NN / 32, BB), 256>>>(PJ(2,0), PJ(2,1), PJ(2,2), pHt0, pHt1);

    // SCA score + softmax + AV (K-split x4)
    gemm_tc<3, 0, 1><<<dim3(NN / 256, NN / 128, BB), 512, SMTC>>>(
        PJ(0,0), PJ(0,1), PJ(0,1), PJ(1,0), PJ(1,1), PJ(1,1),
        CC, FCB, FCB, pS, NN, SNB, 0, nullptr, nullptr, nullptr, nullptr);
    softmax_kernel<<<BB * NN, 256>>>(pS, pMW, pP0, pP1);
    gemm_tc<3, 0, 4><<<dim3(1, NN / 128, BB * 4), 512, SMTC>>>(
        pP0, pP1, pP1, pHt0, pHt1, pHt1,
        NN, SNB, FCB, pOp, CC, FCB, (long)SZF, nullptr, nullptr, nullptr, nullptr);

    // SSA score + argmax
    gemm_tc<6, 0, 1><<<dim3(NN / 256, NN / 128, BB), 512, SMTC>>>(
        PJ(3,0), PJ(3,1), PJ(3,2), PJ(4,0), PJ(4,1), PJ(4,2),
        CC, FCB, FCB, pS, NN, SNB, 0, nullptr, nullptr, nullptr, nullptr);
    argmax_kernel<<<BB * NN, 256>>>(pS, pMW, pIdx);

    // combine -> V splits; final conv + residual
    combine_kernel<<<BB * NN, 256>>>(pOp, PJ(2,0), PJ(2,1), PJ(2,2), pIdx, t1p, t2p, pV0, pV1);
    gemm_tc<3, 2, 1><<<dim3(NN / 256, CC / 128, BB), 512, SMTC>>>(
        WL(3,0), WL(3,1), WL(3,1), pV0, pV1, pV1,
        CC, 0, FCB, out, NN, (long)CC * NN, 0, bo, content, t1p, t2p);
}